// round 10
// baseline (speedup 1.0000x reference)
#include <cuda_runtime.h>

#define NL 16
#define NE 10
#define NC 128
#define NB_TOT 8192
#define NBASIS 968      // 16 linear + 136 pairs + 816 triples (Horner p-major order)
#define MROWD 20        // 10 e-values, each duplicated -> 20 floats = 80B rows
#define TPB 128
#define ROWS 4          // 4 b-rows per thread, as 2 f32x2 row-pairs
#define NPAIR 2
#define MBUF_ROWS 289   // largest chunk (p=0,1)

// chunk row offsets into the 968-row Horner order, grouped by p:
//   [0,2):289  [2,4):225  [4,7):235  [7,11):164  [11,16):55
#define SMEM_M_FLOATS (MBUF_ROWS * MROWD)            // 5780
#define SMEM_X_FLOATS (NL * NPAIR * TPB * 2)         // 8192 (float2 entries)
#define SMEM_BYTES ((SMEM_M_FLOATS + SMEM_X_FLOATS) * 4)   // 23120 + 32768 = 55888

typedef unsigned long long ull;

// Precomputed per-channel basis->element matrix, Horner order, e-duplicated.
__device__ __align__(16) static float g_M[(size_t)NC * NBASIS * MROWD];

__device__ __forceinline__ int id3(int a, int b, int d) { return ((a*NL + b)*NL + d) * 23; }

// ---------------------------------------------------------------------------
// build_M: one thread per (m, c). Decodes Horner-order row index m into
// (type, p, q, i), symmetrizes U over index permutations, contracts with W,
// writes each e-value twice (for row-pair-packed f32x2 FMA in the main kernel).
// ---------------------------------------------------------------------------
__global__ void build_M_kernel(const float* __restrict__ U1, const float* __restrict__ U2,
                               const float* __restrict__ U3, const float* __restrict__ W1,
                               const float* __restrict__ W2, const float* __restrict__ W3) {
    int t = blockIdx.x * blockDim.x + threadIdx.x;
    if (t >= NBASIS * NC) return;
    int m = t >> 7;
    int c = t & (NC - 1);

    // Decode Horner position.
    int p = 0;
    for (;;) {
        int np = NL - p;
        int blk = 1 + np + np * (np + 1) / 2;
        if (m < blk) break;
        m -= blk; p++;
    }
    int type, q = 0, i = 0;
    if (m == 0) {
        type = 1;
    } else {
        m -= 1;
        q = p;
        for (;;) {
            int blk = 1 + (NL - q);
            if (m < blk) break;
            m -= blk; q++;
        }
        if (m == 0) type = 2;
        else { type = 3; i = q + (m - 1); }
    }

    float row[NE];
    if (type == 1) {
        float u = U1[p];                          // K1 == 1
        #pragma unroll
        for (int e = 0; e < NE; e++) row[e] = u * W1[e*NC + c];
    } else if (type == 2) {
        float s[4];
        #pragma unroll
        for (int k = 0; k < 4; k++) {
            float v = U2[(p*NL + q)*4 + k];
            if (p != q) v += U2[(q*NL + p)*4 + k];
            s[k] = v;
        }
        #pragma unroll
        for (int e = 0; e < NE; e++) {
            float a = 0.f;
            #pragma unroll
            for (int k = 0; k < 4; k++) a += s[k] * W2[(e*4 + k)*NC + c];
            row[e] = a;
        }
    } else {
        float s[23];
        for (int k = 0; k < 23; k++) {
            float v = U3[id3(p,q,i) + k];
            if (p < q && q < i) {
                v += U3[id3(p,i,q)+k] + U3[id3(q,p,i)+k] + U3[id3(q,i,p)+k]
                   + U3[id3(i,p,q)+k] + U3[id3(i,q,p)+k];
            } else if (p == q && q < i) {
                v += U3[id3(p,i,p)+k] + U3[id3(i,p,p)+k];
            } else if (p < q && q == i) {
                v += U3[id3(q,p,q)+k] + U3[id3(q,q,p)+k];
            }
            s[k] = v;
        }
        for (int e = 0; e < NE; e++) {
            float a = 0.f;
            for (int k = 0; k < 23; k++) a += s[k] * W3[(e*23 + k)*NC + c];
            row[e] = a;
        }
    }

    int mrow = t >> 7;
    float* dst = g_M + ((size_t)c * NBASIS + mrow) * MROWD;
    #pragma unroll
    for (int e = 0; e < NE; e++) { dst[2*e] = row[e]; dst[2*e + 1] = row[e]; }
}

// ---------------------------------------------------------------------------
// Packed fp32x2 helpers.
// ---------------------------------------------------------------------------
__device__ __forceinline__ void ffma2(ull& d, ull a, ull b) {
    asm("fma.rn.f32x2 %0, %1, %2, %0;" : "+l"(d) : "l"(a), "l"(b));
}
__device__ __forceinline__ ull mul2(ull a, ull b) {
    ull r;
    asm("mul.rn.f32x2 %0, %1, %2;" : "=l"(r) : "l"(a), "l"(b));
    return r;
}

struct R10 { ull v[10]; };

// Load one duplicated M row (80B) with five 16B shared loads (broadcast).
__device__ __forceinline__ R10 ldrow(const float* mp) {
    R10 r;
    const ulonglong2* u = reinterpret_cast<const ulonglong2*>(mp);
    #pragma unroll
    for (int k = 0; k < 5; k++) {
        ulonglong2 w = u[k];
        r.v[2*k]   = w.x;
        r.v[2*k+1] = w.y;
    }
    return r;
}
__device__ __forceinline__ void fma10(R10& a, ull d, const R10& m) {
    #pragma unroll
    for (int k = 0; k < 10; k++) ffma2(a.v[k], d, m.v[k]);
}
__device__ __forceinline__ void zero10(R10& a) {
    #pragma unroll
    for (int k = 0; k < 10; k++) a.v[k] = 0ull;
}

// ---------------------------------------------------------------------------
// 2-level Horner over p in [P0, P1):
//   acc[pi] += xpair_p[pi]*M1  +  (xpair_p*xpair_q)[pi] * (M2 + sum_i xpair_i[pi]*M3)
// sx: packed x pairs, entry ((i*2+pi)*TPB) relative to the thread's base.
// ---------------------------------------------------------------------------
template<int P0, int P1>
__device__ __forceinline__ void horner_span(const float* __restrict__ sM,
                                            const ull* __restrict__ sx,
                                            R10& acc0, R10& acc1) {
    const float* mp = sM;
    #pragma unroll
    for (int p = P0; p < P1; p++) {
        ull xp0 = sx[(p*NPAIR + 0) * TPB];
        ull xp1 = sx[(p*NPAIR + 1) * TPB];
        {
            R10 m1 = ldrow(mp); mp += MROWD;
            fma10(acc0, xp0, m1);
            fma10(acc1, xp1, m1);
        }
        #pragma unroll
        for (int q = p; q < NL; q++) {
            ull xq0 = sx[(q*NPAIR + 0) * TPB];
            ull xq1 = sx[(q*NPAIR + 1) * TPB];
            R10 s0 = ldrow(mp); mp += MROWD;     // M2[p,q]
            R10 s1 = s0;
            #pragma unroll
            for (int i = q; i < NL; i++) {
                R10 m3 = ldrow(mp); mp += MROWD;
                fma10(s0, sx[(i*NPAIR + 0) * TPB], m3);
                fma10(s1, sx[(i*NPAIR + 1) * TPB], m3);
            }
            fma10(acc0, mul2(xp0, xq0), s0);
            fma10(acc1, mul2(xp1, xq1), s1);
        }
    }
}

__device__ __forceinline__ void stage(float* __restrict__ dst, const float* __restrict__ src,
                                      int nfloats, int tid) {
    const float4* s4 = reinterpret_cast<const float4*>(src);
    float4* d4 = reinterpret_cast<float4*>(dst);
    int n4 = nfloats / 4;
    for (int j = tid; j < n4; j += TPB) d4[j] = s4[j];
}

__device__ __forceinline__ void epilogue_pair(const R10& a, int blo, int bhi, int c,
                                              const float* __restrict__ y,
                                              float* __restrict__ out) {
    const float* ylo = y + (size_t)blo * NE;
    const float* yhi = y + (size_t)bhi * NE;
    float rlo = 0.f, rhi = 0.f;
    #pragma unroll
    for (int e = 0; e < NE; e++) {
        float lo, hi;
        asm("mov.b64 {%0, %1}, %2;" : "=f"(lo), "=f"(hi) : "l"(a.v[e]));
        rlo += lo * ylo[e];
        rhi += hi * yhi[e];
    }
    out[(size_t)blo * NC + c] = rlo;
    out[(size_t)bhi * NC + c] = rhi;
}

// ---------------------------------------------------------------------------
// Main kernel. Row-pair f32x2 packing: the FFMA2 multiplier is the packed
// (x_r0, x_r1) pair straight from one LDS.64 (no dup MOVs); M is read
// pre-duplicated (5 broadcast LDS.128 per basis row). Per triple basis:
// 7 LDS + 20 FFMA2 -> FMA pipe binds instead of the smem crossbar.
// M[c] is streamed through a 23.1KB smem buffer in 5 chunks; x pairs in smem.
// 4 CTAs/SM (128-reg cap, 55.9KB dynamic smem each).
// ---------------------------------------------------------------------------
__global__ __launch_bounds__(TPB, 4)
void contract_kernel(const float* __restrict__ x, const float* __restrict__ y,
                     float* __restrict__ out) {
    extern __shared__ __align__(16) float smem[];
    float* sM = smem;                              // MBUF_ROWS * MROWD floats
    float2* sx = reinterpret_cast<float2*>(smem + SMEM_M_FLOATS);  // [NL][NPAIR][TPB]

    const int c   = blockIdx.y;
    const int b0  = blockIdx.x * (TPB * ROWS);
    const int tid = threadIdx.x;

    // Load this thread's 4 x rows and write packed row-pairs into smem.
    {
        float xv[ROWS][NL];
        #pragma unroll
        for (int r = 0; r < ROWS; r++) {
            const float4* xr = reinterpret_cast<const float4*>(
                x + ((size_t)(b0 + r * TPB + tid) * NC + c) * NL);
            #pragma unroll
            for (int j = 0; j < 4; j++) {
                float4 v = xr[j];
                xv[r][4*j+0] = v.x; xv[r][4*j+1] = v.y;
                xv[r][4*j+2] = v.z; xv[r][4*j+3] = v.w;
            }
        }
        #pragma unroll
        for (int i = 0; i < NL; i++) {
            sx[(i*NPAIR + 0)*TPB + tid] = make_float2(xv[0][i], xv[1][i]);
            sx[(i*NPAIR + 1)*TPB + tid] = make_float2(xv[2][i], xv[3][i]);
        }
    }

    R10 acc0, acc1;
    zero10(acc0); zero10(acc1);

    const float* gM = g_M + (size_t)c * NBASIS * MROWD;
    const ull* sxp = reinterpret_cast<const ull*>(sx) + tid;

    // Chunked Horner: row counts 289, 225, 235, 164, 55 (offsets 0/289/514/749/913).
    stage(sM, gM + 0ull,            289 * MROWD, tid);
    __syncthreads();
    horner_span<0, 2>(sM, sxp, acc0, acc1);
    __syncthreads();

    stage(sM, gM + 289ull * MROWD,  225 * MROWD, tid);
    __syncthreads();
    horner_span<2, 4>(sM, sxp, acc0, acc1);
    __syncthreads();

    stage(sM, gM + 514ull * MROWD,  235 * MROWD, tid);
    __syncthreads();
    horner_span<4, 7>(sM, sxp, acc0, acc1);
    __syncthreads();

    stage(sM, gM + 749ull * MROWD,  164 * MROWD, tid);
    __syncthreads();
    horner_span<7, 11>(sM, sxp, acc0, acc1);
    __syncthreads();

    stage(sM, gM + 913ull * MROWD,   55 * MROWD, tid);
    __syncthreads();
    horner_span<11, NL>(sM, sxp, acc0, acc1);

    epilogue_pair(acc0, b0 + tid,           b0 + TPB + tid,     c, y, out);
    epilogue_pair(acc1, b0 + 2*TPB + tid,   b0 + 3*TPB + tid,   c, y, out);
}

// ---------------------------------------------------------------------------
extern "C" void kernel_launch(void* const* d_in, const int* in_sizes, int n_in,
                              void* d_out, int out_size) {
    const float *x = 0, *y = 0, *U1 = 0, *U2 = 0, *U3 = 0, *W1 = 0, *W2 = 0, *W3 = 0;
    for (int i = 0; i < n_in; i++) {
        const float* p = (const float*)d_in[i];
        switch (in_sizes[i]) {
            case 8192 * 128 * 16:   x  = p; break;   // (B,C,L)
            case 8192 * 10:         y  = p; break;   // (B,E)
            case 16:                U1 = p; break;   // (L,K1)
            case 16 * 16 * 4:       U2 = p; break;   // (L,L,K2)
            case 16 * 16 * 16 * 23: U3 = p; break;   // (L,L,L,K3)
            case 10 * 1 * 128:      W1 = p; break;   // (E,K1,C)
            case 10 * 4 * 128:      W2 = p; break;   // (E,K2,C)
            case 10 * 23 * 128:     W3 = p; break;   // (E,K3,C)
        }
    }

    cudaFuncSetAttribute(contract_kernel,
                         cudaFuncAttributeMaxDynamicSharedMemorySize, SMEM_BYTES);

    const int tot = NBASIS * NC;
    build_M_kernel<<<(tot + 255) / 256, 256>>>(U1, U2, U3, W1, W2, W3);

    dim3 grid(NB_TOT / (TPB * ROWS), NC);   // (16, 128)
    contract_kernel<<<grid, TPB, SMEM_BYTES>>>(x, y, (float*)d_out);
}

// round 11
// speedup vs baseline: 1.1242x; 1.1242x over previous
#include <cuda_runtime.h>

#define NL 16
#define NE 10
#define NC 128
#define NB_TOT 8192
#define NBASIS 968      // 16 linear + 136 pairs + 816 triples (Horner order)
#define MROW 12         // 10 floats padded to 12 (48B rows, 16B aligned)
#define TPB 128
#define ROWS 4

typedef unsigned long long ull;

// Precomputed per-channel basis->element matrix in Horner traversal order.
__device__ __align__(16) static float g_M[(size_t)NC * NBASIS * MROW];

__device__ __forceinline__ int id3(int a, int b, int d) { return ((a*NL + b)*NL + d) * 23; }

// ---------------------------------------------------------------------------
// build_M: one thread per (m, c). Decodes Horner-order row index m into
// (type, p, q, i), symmetrizes U over index permutations, contracts with W.
// Horner order: for p { M1(p); for q>=p { M2(p,q); for i>=q { M3(p,q,i) } } }
// ---------------------------------------------------------------------------
__global__ void build_M_kernel(const float* __restrict__ U1, const float* __restrict__ U2,
                               const float* __restrict__ U3, const float* __restrict__ W1,
                               const float* __restrict__ W2, const float* __restrict__ W3) {
    int t = blockIdx.x * blockDim.x + threadIdx.x;
    if (t >= NBASIS * NC) return;
    int m = t >> 7;
    int c = t & (NC - 1);

    // Decode Horner position.
    int p = 0;
    for (;;) {
        int np = NL - p;                         // #q values
        int blk = 1 + np + np * (np + 1) / 2;    // M1 + per-q (M2 + triples)
        if (m < blk) break;
        m -= blk; p++;
    }
    int type, q = 0, i = 0;
    if (m == 0) {
        type = 1;
    } else {
        m -= 1;
        q = p;
        for (;;) {
            int blk = 1 + (NL - q);
            if (m < blk) break;
            m -= blk; q++;
        }
        if (m == 0) type = 2;
        else { type = 3; i = q + (m - 1); }
    }

    float row[NE];
    if (type == 1) {
        float u = U1[p];                          // K1 == 1
        #pragma unroll
        for (int e = 0; e < NE; e++) row[e] = u * W1[e*NC + c];
    } else if (type == 2) {
        float s[4];
        #pragma unroll
        for (int k = 0; k < 4; k++) {
            float v = U2[(p*NL + q)*4 + k];
            if (p != q) v += U2[(q*NL + p)*4 + k];
            s[k] = v;
        }
        #pragma unroll
        for (int e = 0; e < NE; e++) {
            float a = 0.f;
            #pragma unroll
            for (int k = 0; k < 4; k++) a += s[k] * W2[(e*4 + k)*NC + c];
            row[e] = a;
        }
    } else {
        float s[23];
        for (int k = 0; k < 23; k++) {
            float v = U3[id3(p,q,i) + k];
            if (p < q && q < i) {
                v += U3[id3(p,i,q)+k] + U3[id3(q,p,i)+k] + U3[id3(q,i,p)+k]
                   + U3[id3(i,p,q)+k] + U3[id3(i,q,p)+k];
            } else if (p == q && q < i) {
                v += U3[id3(p,i,p)+k] + U3[id3(i,p,p)+k];
            } else if (p < q && q == i) {
                v += U3[id3(q,p,q)+k] + U3[id3(q,q,p)+k];
            }
            s[k] = v;
        }
        for (int e = 0; e < NE; e++) {
            float a = 0.f;
            for (int k = 0; k < 23; k++) a += s[k] * W3[(e*23 + k)*NC + c];
            row[e] = a;
        }
    }

    int mrow = t >> 7;
    float* dst = g_M + ((size_t)c * NBASIS + mrow) * MROW;
    #pragma unroll
    for (int e = 0; e < NE; e++) dst[e] = row[e];
    dst[10] = 0.f;
    dst[11] = 0.f;
}

// ---------------------------------------------------------------------------
// Packed fp32x2 helpers.
// ---------------------------------------------------------------------------
__device__ __forceinline__ void ffma2(ull& d, ull a, ull b) {
    asm("fma.rn.f32x2 %0, %1, %2, %0;" : "+l"(d) : "l"(a), "l"(b));
}
__device__ __forceinline__ ull dup2(float v) {
    ull r;
    asm("mov.b64 %0, {%1, %1};" : "=l"(r) : "f"(v));
    return r;
}

struct Row { ull a, b, c, d, e; };

__device__ __forceinline__ Row load_row(const float* mp) {
    ulonglong2 u0 = *reinterpret_cast<const ulonglong2*>(mp);
    ulonglong2 u1 = *reinterpret_cast<const ulonglong2*>(mp + 4);
    ull u2 = *reinterpret_cast<const ull*>(mp + 8);
    Row r; r.a = u0.x; r.b = u0.y; r.c = u1.x; r.d = u1.y; r.e = u2;
    return r;
}
__device__ __forceinline__ void fma_row(Row& acc, ull d, const Row& m) {
    ffma2(acc.a, d, m.a);
    ffma2(acc.b, d, m.b);
    ffma2(acc.c, d, m.c);
    ffma2(acc.d, d, m.d);
    ffma2(acc.e, d, m.e);
}
__device__ __forceinline__ void zero_row(Row& r) {
    r.a = r.b = r.c = r.d = r.e = 0ull;
}

__device__ __forceinline__ void epilogue_row(const Row& a, int b, int c,
                                             const float* __restrict__ y,
                                             float* __restrict__ out) {
    const float* yb = y + (size_t)b * NE;
    ull v[5] = {a.a, a.b, a.c, a.d, a.e};
    float res = 0.f;
    #pragma unroll
    for (int k = 0; k < 5; k++) {
        float lo, hi;
        asm("mov.b64 {%0, %1}, %2;" : "=f"(lo), "=f"(hi) : "l"(v[k]));
        res += lo * yb[2*k];
        res += hi * yb[2*k + 1];
    }
    out[(size_t)b * NC + c] = res;
}

// ---------------------------------------------------------------------------
// Main kernel: 3-level Horner, ROWS=4 b-rows per thread, one channel c.
// Per triple basis: 3 broadcast LDS vs 20 FFMA2 -> FMA pipe binds (ratio 1.7x).
// __launch_bounds__(TPB, 2): 256-reg ceiling so the ~190-reg demand does NOT
// spill (the R6 failure). 2 CTAs/SM; full M[c] (46.5KB) staged per CTA.
// ---------------------------------------------------------------------------
__global__ __launch_bounds__(TPB, 2)
void contract_kernel(const float* __restrict__ x, const float* __restrict__ y,
                     float* __restrict__ out) {
    __shared__ __align__(16) float sM[NBASIS * MROW];

    const int c   = blockIdx.y;
    const int b0  = blockIdx.x * (TPB * ROWS);
    const int tid = threadIdx.x;

    // Stage M[c] into shared (float4, broadcast-reused by all warps).
    {
        const float4* src = reinterpret_cast<const float4*>(g_M + (size_t)c * NBASIS * MROW);
        float4* dst = reinterpret_cast<float4*>(sM);
        const int n4 = NBASIS * MROW / 4;   // 2904
        for (int j = tid; j < n4; j += TPB) dst[j] = src[j];
    }

    // Load the thread's four x rows straight into registers.
    float xv[ROWS][NL];
    #pragma unroll
    for (int r = 0; r < ROWS; r++) {
        const float4* xr = reinterpret_cast<const float4*>(
            x + ((size_t)(b0 + r * TPB + tid) * NC + c) * NL);
        #pragma unroll
        for (int j = 0; j < 4; j++) {
            float4 v = xr[j];
            xv[r][4*j+0] = v.x; xv[r][4*j+1] = v.y;
            xv[r][4*j+2] = v.z; xv[r][4*j+3] = v.w;
        }
    }
    __syncthreads();

    Row acc[ROWS];
    #pragma unroll
    for (int r = 0; r < ROWS; r++) zero_row(acc[r]);

    const float* mp = sM;
    #pragma unroll
    for (int p = 0; p < NL; p++) {
        Row ap[ROWS];
        {
            Row m1 = load_row(mp);       // M1[p]
            mp += MROW;
            #pragma unroll
            for (int r = 0; r < ROWS; r++) ap[r] = m1;
        }
        #pragma unroll
        for (int q = p; q < NL; q++) {
            Row s[ROWS];
            {
                Row m2 = load_row(mp);   // M2[p,q]
                mp += MROW;
                #pragma unroll
                for (int r = 0; r < ROWS; r++) s[r] = m2;
            }
            #pragma unroll
            for (int i = q; i < NL; i++) {
                Row m3 = load_row(mp);
                mp += MROW;
                #pragma unroll
                for (int r = 0; r < ROWS; r++)
                    fma_row(s[r], dup2(xv[r][i]), m3);
            }
            #pragma unroll
            for (int r = 0; r < ROWS; r++)
                fma_row(ap[r], dup2(xv[r][q]), s[r]);
        }
        #pragma unroll
        for (int r = 0; r < ROWS; r++)
            fma_row(acc[r], dup2(xv[r][p]), ap[r]);
    }

    #pragma unroll
    for (int r = 0; r < ROWS; r++)
        epilogue_row(acc[r], b0 + r * TPB + tid, c, y, out);
}

// ---------------------------------------------------------------------------
extern "C" void kernel_launch(void* const* d_in, const int* in_sizes, int n_in,
                              void* d_out, int out_size) {
    const float *x = 0, *y = 0, *U1 = 0, *U2 = 0, *U3 = 0, *W1 = 0, *W2 = 0, *W3 = 0;
    for (int i = 0; i < n_in; i++) {
        const float* p = (const float*)d_in[i];
        switch (in_sizes[i]) {
            case 8192 * 128 * 16:   x  = p; break;   // (B,C,L)
            case 8192 * 10:         y  = p; break;   // (B,E)
            case 16:                U1 = p; break;   // (L,K1)
            case 16 * 16 * 4:       U2 = p; break;   // (L,L,K2)
            case 16 * 16 * 16 * 23: U3 = p; break;   // (L,L,L,K3)
            case 10 * 1 * 128:      W1 = p; break;   // (E,K1,C)
            case 10 * 4 * 128:      W2 = p; break;   // (E,K2,C)
            case 10 * 23 * 128:     W3 = p; break;   // (E,K3,C)
        }
    }

    const int tot = NBASIS * NC;
    build_M_kernel<<<(tot + 255) / 256, 256>>>(U1, U2, U3, W1, W2, W3);

    dim3 grid(NB_TOT / (TPB * ROWS), NC);   // (16, 128)
    contract_kernel<<<grid, TPB>>>(x, y, (float*)d_out);
}